// round 2
// baseline (speedup 1.0000x reference)
#include <cuda_runtime.h>

#define NN 2048
#define BB 64
#define CC 64
#define EE 16
#define KIO 12288   // 3*64*64
#define BNC (BB*NN*CC)

// ---------------- scratch (device globals; no allocations allowed) ----------------
__device__ __align__(128) float g_ne[NN*EE];        // 128 KB
__device__ __align__(128) float g_S [NN*NN];        // 16.8 MB
__device__ __align__(128) float g_Z1[BNC];          // 33.5 MB
__device__ __align__(128) float g_Z2[BNC];          // 33.5 MB
__device__ __align__(128) float g_W [NN*KIO];       // 100 MB
__device__ __align__(128) float g_bias[NN*CC];      // 512 KB

// ---------------- packed fp32x2 helpers (sm_103a FFMA2 path) ----------------
__device__ __forceinline__ unsigned long long ffma2(unsigned long long a,
                                                    unsigned long long b,
                                                    unsigned long long c) {
    unsigned long long d;
    asm("fma.rn.f32x2 %0, %1, %2, %3;" : "=l"(d) : "l"(a), "l"(b), "l"(c));
    return d;
}
__device__ __forceinline__ unsigned long long pack2(float x, float y) {
    unsigned long long r;
    asm("mov.b64 %0, {%1, %2};" : "=l"(r) : "f"(x), "f"(y));
    return r;
}

// ---------------- 1) layernorm over E=16 ----------------
__global__ void ln_kernel(const float* __restrict__ nemb, const float* __restrict__ temb,
                          const float* __restrict__ gamma, const float* __restrict__ beta) {
    int row = blockIdx.x * blockDim.x + threadIdx.x;
    if (row >= NN) return;
    float v[EE];
    float s = 0.f;
    #pragma unroll
    for (int e = 0; e < EE; e++) {
        float x = nemb[row*EE + e] + temb[e];
        v[e] = x; s += x;
    }
    float mu = s * (1.f/EE);
    float s2 = 0.f;
    #pragma unroll
    for (int e = 0; e < EE; e++) { float d = v[e] - mu; s2 += d*d; }
    float inv = rsqrtf(s2 * (1.f/EE) + 1e-12f);
    #pragma unroll
    for (int e = 0; e < EE; e++)
        g_ne[row*EE + e] = (v[e] - mu) * inv * gamma[e] + beta[e];
}

// ---------------- 2) row softmax of ne @ ne^T -> g_S ----------------
__global__ void softmax_kernel() {
    const int n   = blockIdx.x;
    const int tid = threadIdx.x;
    __shared__ float nrow[EE];
    __shared__ float red[8];
    if (tid < EE) nrow[tid] = g_ne[n*EE + tid];
    __syncthreads();

    float l[8];
    float mx = -3.4e38f;
    #pragma unroll
    for (int i = 0; i < 8; i++) {
        int m = tid + i*256;
        const float4* p = (const float4*)&g_ne[m*EE];
        float4 q0 = p[0], q1 = p[1], q2 = p[2], q3 = p[3];
        float d = q0.x*nrow[0] + q0.y*nrow[1] + q0.z*nrow[2] + q0.w*nrow[3]
                + q1.x*nrow[4] + q1.y*nrow[5] + q1.z*nrow[6] + q1.w*nrow[7]
                + q2.x*nrow[8] + q2.y*nrow[9] + q2.z*nrow[10]+ q2.w*nrow[11]
                + q3.x*nrow[12]+ q3.y*nrow[13]+ q3.z*nrow[14]+ q3.w*nrow[15];
        l[i] = d;
        mx = fmaxf(mx, d);
    }
    int lane = tid & 31, wid = tid >> 5;
    #pragma unroll
    for (int o = 16; o; o >>= 1) mx = fmaxf(mx, __shfl_xor_sync(0xffffffffu, mx, o));
    if (lane == 0) red[wid] = mx;
    __syncthreads();
    float bm = red[0];
    #pragma unroll
    for (int w = 1; w < 8; w++) bm = fmaxf(bm, red[w]);

    float s = 0.f;
    #pragma unroll
    for (int i = 0; i < 8; i++) { l[i] = __expf(l[i] - bm); s += l[i]; }
    #pragma unroll
    for (int o = 16; o; o >>= 1) s += __shfl_xor_sync(0xffffffffu, s, o);
    __syncthreads();
    if (lane == 0) red[wid] = s;
    __syncthreads();
    float ts = red[0];
    #pragma unroll
    for (int w = 1; w < 8; w++) ts += red[w];
    float inv = 1.f / ts;
    #pragma unroll
    for (int i = 0; i < 8; i++) g_S[n*NN + tid + i*256] = l[i] * inv;
}

// ---------------- 3a) per-node weights: g_W[n, kio] = sum_e ne[n,e] * Wp[e, kio] ----------------
__global__ void wpool_kernel(const float* __restrict__ wpool) {
    __shared__ float wp[EE][64];
    const int tid  = threadIdx.x;
    const int coff = blockIdx.x * 64;   // 192 blocks cover KIO=12288
    #pragma unroll
    for (int q = 0; q < 4; q++) {
        int idx = tid + q*256;          // 0..1023
        int e = idx >> 6, c = idx & 63;
        wp[e][c] = wpool[e*KIO + coff + c];
    }
    __syncthreads();
    const int r = tid >> 6;   // 0..3
    const int c = tid & 63;
    for (int n0 = 0; n0 < NN; n0 += 4) {
        int n = n0 + r;
        const float* ner = &g_ne[n*EE];
        float acc = 0.f;
        #pragma unroll
        for (int e = 0; e < EE; e++) acc = fmaf(ner[e], wp[e][c], acc);
        g_W[(size_t)n*KIO + coff + c] = acc;
    }
}

// ---------------- 3b) per-node bias: g_bias = ne @ bias_pool ----------------
__global__ void biasp_kernel(const float* __restrict__ bpool) {
    int idx = blockIdx.x * 256 + threadIdx.x;   // 512 blocks -> 131072
    int n = idx >> 6, o = idx & 63;
    float a = 0.f;
    #pragma unroll
    for (int e = 0; e < EE; e++) a = fmaf(g_ne[n*EE + e], bpool[e*64 + o], a);
    g_bias[idx] = a;
}

// ---------------- 4) Z = S @ Xin  (Xin layout [B,N,C]; cols j=(b,c)) ----------------
// stage 0: Xin = x (input), Zout = g_Z1 ; stage 1: Xin = g_Z1, Zout = g_Z2
__global__ __launch_bounds__(256, 2) void gemm_sx(const float* __restrict__ xin_param, int stage) {
    __shared__ __align__(16) float As[2][16][128];
    __shared__ __align__(16) float Bs[2][16][128];

    const float* __restrict__ Xin = (stage == 0) ? xin_param : (const float*)g_Z1;
    float* __restrict__ Zout      = (stage == 0) ? (float*)g_Z1 : (float*)g_Z2;

    const int tid = threadIdx.x;
    const int n0  = blockIdx.x * 128;   // 16 tiles over N
    const int jt  = blockIdx.y;         // 32 tiles over 4096 = B*C
    const int tx  = tid & 15;
    const int ty  = tid >> 4;

    // global load decode (f = tid*2 + q)
    const int fa_row0 = (tid*2) >> 2;         // A: row = f>>2, kk4=(f&3)*4
    const int fa_kk0  = ((tid*2) & 3) * 4;
    const int fa_row1 = (tid*2 + 1) >> 2;
    const int fa_kk1  = ((tid*2 + 1) & 3) * 4;
    const int fb_r0   = (tid*2) >> 5;         // B: row=f>>5, jl4=(f&31)*4
    const int fb_j0   = ((tid*2) & 31) * 4;
    const int fb_r1   = (tid*2 + 1) >> 5;
    const int fb_j1   = ((tid*2 + 1) & 31) * 4;

    const int jg0 = jt*128 + fb_j0;  const int b_0 = jg0 >> 6, c_0 = jg0 & 63;
    const int jg1 = jt*128 + fb_j1;  const int b_1 = jg1 >> 6, c_1 = jg1 & 63;

    unsigned long long acc[8][4];
    #pragma unroll
    for (int i = 0; i < 8; i++)
        #pragma unroll
        for (int j = 0; j < 4; j++) acc[i][j] = 0ull;

    float4 pa0, pa1, pb0, pb1;
    // prologue: stage 0 tile
    pa0 = *(const float4*)&g_S[(size_t)(n0 + fa_row0)*NN + fa_kk0];
    pa1 = *(const float4*)&g_S[(size_t)(n0 + fa_row1)*NN + fa_kk1];
    pb0 = *(const float4*)&Xin[(size_t)b_0*NN*CC + fb_r0*CC + c_0];
    pb1 = *(const float4*)&Xin[(size_t)b_1*NN*CC + fb_r1*CC + c_1];
    As[0][fa_kk0+0][fa_row0]=pa0.x; As[0][fa_kk0+1][fa_row0]=pa0.y;
    As[0][fa_kk0+2][fa_row0]=pa0.z; As[0][fa_kk0+3][fa_row0]=pa0.w;
    As[0][fa_kk1+0][fa_row1]=pa1.x; As[0][fa_kk1+1][fa_row1]=pa1.y;
    As[0][fa_kk1+2][fa_row1]=pa1.z; As[0][fa_kk1+3][fa_row1]=pa1.w;
    *(float4*)&Bs[0][fb_r0][fb_j0] = pb0;
    *(float4*)&Bs[0][fb_r1][fb_j1] = pb1;
    __syncthreads();

    int cur = 0;
    for (int kt = 0; kt < 128; kt++) {
        const int k0n = (kt + 1) * 16;
        if (kt < 127) {
            pa0 = *(const float4*)&g_S[(size_t)(n0 + fa_row0)*NN + k0n + fa_kk0];
            pa1 = *(const float4*)&g_S[(size_t)(n0 + fa_row1)*NN + k0n + fa_kk1];
            pb0 = *(const float4*)&Xin[(size_t)b_0*NN*CC + (k0n + fb_r0)*CC + c_0];
            pb1 = *(const float4*)&Xin[(size_t)b_1*NN*CC + (k0n + fb_r1)*CC + c_1];
        }
        #pragma unroll
        for (int kk = 0; kk < 16; kk++) {
            float4 a0 = *(const float4*)&As[cur][kk][ty*4];
            float4 a1 = *(const float4*)&As[cur][kk][ty*4 + 64];
            ulonglong2 bq0 = *(const ulonglong2*)&Bs[cur][kk][tx*4];
            ulonglong2 bq1 = *(const ulonglong2*)&Bs[cur][kk][tx*4 + 64];
            unsigned long long bp[4] = { bq0.x, bq0.y, bq1.x, bq1.y };
            float av[8] = { a0.x,a0.y,a0.z,a0.w, a1.x,a1.y,a1.z,a1.w };
            #pragma unroll
            for (int i = 0; i < 8; i++) {
                unsigned long long ad = pack2(av[i], av[i]);
                #pragma unroll
                for (int jp = 0; jp < 4; jp++)
                    acc[i][jp] = ffma2(ad, bp[jp], acc[i][jp]);
            }
        }
        if (kt < 127) {
            const int nxt = cur ^ 1;
            As[nxt][fa_kk0+0][fa_row0]=pa0.x; As[nxt][fa_kk0+1][fa_row0]=pa0.y;
            As[nxt][fa_kk0+2][fa_row0]=pa0.z; As[nxt][fa_kk0+3][fa_row0]=pa0.w;
            As[nxt][fa_kk1+0][fa_row1]=pa1.x; As[nxt][fa_kk1+1][fa_row1]=pa1.y;
            As[nxt][fa_kk1+2][fa_row1]=pa1.z; As[nxt][fa_kk1+3][fa_row1]=pa1.w;
            *(float4*)&Bs[nxt][fb_r0][fb_j0] = pb0;
            *(float4*)&Bs[nxt][fb_r1][fb_j1] = pb1;
            __syncthreads();
            cur = nxt;
        }
    }

    // epilogue: rows n0 + ty*4 + (i&3) + (i>>2)*64 ; col pairs jp -> batch jt*2+(jp>>1), c=tx*4+(jp&1)*2
    #pragma unroll
    for (int i = 0; i < 8; i++) {
        int n = n0 + ty*4 + (i & 3) + (i >> 2) * 64;
        #pragma unroll
        for (int jp = 0; jp < 4; jp++) {
            int b = jt*2 + (jp >> 1);
            int c = tx*4 + (jp & 1) * 2;
            *(unsigned long long*)&Zout[(size_t)b*NN*CC + n*CC + c] = acc[i][jp];
        }
    }
}

// ---------------- 5) epilogue: Y[b,n,o] = XG[b,:] @ W_n + bias_n ----------------
// XG[b][0:64]=X, [64:128]=Z1, [128:192]=2*Z2 - X
#define XGS 196
#define FIN_SMEM ((KIO + BB*XGS) * 4)

__global__ __launch_bounds__(256, 2) void final_kernel(const float* __restrict__ X,
                                                       float* __restrict__ out) {
    extern __shared__ __align__(16) float sm[];
    float* Ws = sm;            // [192][64]
    float* XG = sm + KIO;      // [64][XGS]
    const int n   = blockIdx.x;
    const int tid = threadIdx.x;

    const float4* wsrc = (const float4*)(g_W + (size_t)n*KIO);
    float4* wdst = (float4*)Ws;
    #pragma unroll
    for (int q = 0; q < 12; q++) wdst[tid + q*256] = wsrc[tid + q*256];

    #pragma unroll
    for (int q = 0; q < 4; q++) {
        int f = tid + q*256;          // 0..1023
        int b = f >> 4, c4 = (f & 15) * 4;
        size_t off = (size_t)b*NN*CC + (size_t)n*CC + c4;
        float4 xv = *(const float4*)&X[off];
        float4 z1 = *(const float4*)&g_Z1[off];
        float4 z2 = *(const float4*)&g_Z2[off];
        float4 g2;
        g2.x = 2.f*z2.x - xv.x; g2.y = 2.f*z2.y - xv.y;
        g2.z = 2.f*z2.z - xv.z; g2.w = 2.f*z2.w - xv.w;
        *(float4*)&XG[b*XGS + c4]       = xv;
        *(float4*)&XG[b*XGS + 64 + c4]  = z1;
        *(float4*)&XG[b*XGS + 128 + c4] = g2;
    }
    __syncthreads();

    const int tx = tid & 7, o0 = tx * 8;
    const int b0 = (tid >> 3) * 2;

    unsigned long long acc[2][4];
    {
        const ulonglong2* bp = (const ulonglong2*)(g_bias + (size_t)n*CC + o0);
        ulonglong2 p0 = bp[0], p1 = bp[1];
        acc[0][0]=p0.x; acc[0][1]=p0.y; acc[0][2]=p1.x; acc[0][3]=p1.y;
        acc[1][0]=p0.x; acc[1][1]=p0.y; acc[1][2]=p1.x; acc[1][3]=p1.y;
    }
    const float* xr0 = &XG[b0*XGS];
    const float* xr1 = &XG[(b0+1)*XGS];
    #pragma unroll 4
    for (int i = 0; i < 192; i++) {
        ulonglong2 w0 = *(const ulonglong2*)&Ws[i*64 + o0];
        ulonglong2 w1 = *(const ulonglong2*)&Ws[i*64 + o0 + 4];
        unsigned long long x0 = pack2(xr0[i], xr0[i]);
        unsigned long long x1 = pack2(xr1[i], xr1[i]);
        acc[0][0] = ffma2(x0, w0.x, acc[0][0]);
        acc[0][1] = ffma2(x0, w0.y, acc[0][1]);
        acc[0][2] = ffma2(x0, w1.x, acc[0][2]);
        acc[0][3] = ffma2(x0, w1.y, acc[0][3]);
        acc[1][0] = ffma2(x1, w0.x, acc[1][0]);
        acc[1][1] = ffma2(x1, w0.y, acc[1][1]);
        acc[1][2] = ffma2(x1, w1.x, acc[1][2]);
        acc[1][3] = ffma2(x1, w1.y, acc[1][3]);
    }
    #pragma unroll
    for (int bb = 0; bb < 2; bb++)
        #pragma unroll
        for (int jp = 0; jp < 4; jp++)
            *(unsigned long long*)&out[(size_t)(b0+bb)*NN*CC + (size_t)n*CC + o0 + jp*2] = acc[bb][jp];
}

// ---------------- launcher ----------------
extern "C" void kernel_launch(void* const* d_in, const int* in_sizes, int n_in,
                              void* d_out, int out_size) {
    const float* x     = (const float*)d_in[0];
    const float* nemb  = (const float*)d_in[1];
    const float* temb  = (const float*)d_in[2];
    const float* wpool = (const float*)d_in[3];
    const float* bpool = (const float*)d_in[4];
    const float* gamma = (const float*)d_in[5];
    const float* beta  = (const float*)d_in[6];
    float* out = (float*)d_out;

    cudaFuncSetAttribute(final_kernel, cudaFuncAttributeMaxDynamicSharedMemorySize, FIN_SMEM);

    ln_kernel<<<16, 128>>>(nemb, temb, gamma, beta);
    softmax_kernel<<<NN, 256>>>();
    wpool_kernel<<<192, 256>>>(wpool);
    biasp_kernel<<<512, 256>>>(bpool);
    dim3 gg(16, 32);
    gemm_sx<<<gg, 256>>>(x, 0);
    gemm_sx<<<gg, 256>>>(x, 1);
    final_kernel<<<NN, 256, FIN_SMEM>>>(x, out);
}

// round 13
// speedup vs baseline: 1.8623x; 1.8623x over previous
#include <cuda_runtime.h>
#include <cuda_bf16.h>
#include <cstdint>

#define NN 2048
#define BB 64
#define CC 64
#define EE 16
#define KIO 12288   // 3*64*64
#define BNC (BB*NN*CC)
#define JJ  (BB*CC)   // 4096

// ---------------- scratch (device globals; no allocations allowed) ----------------
__device__ __align__(128) float g_ne[NN*EE];
__device__ __align__(128) __nv_bfloat16 g_Shi[NN*NN];
__device__ __align__(128) __nv_bfloat16 g_Slo[NN*NN];
__device__ __align__(128) __nv_bfloat16 g_Xthi[(size_t)JJ*NN];
__device__ __align__(128) __nv_bfloat16 g_Xtlo[(size_t)JJ*NN];
__device__ __align__(128) __nv_bfloat16 g_Z1thi[(size_t)JJ*NN];
__device__ __align__(128) __nv_bfloat16 g_Z1tlo[(size_t)JJ*NN];
__device__ __align__(128) float g_Z1[BNC];
__device__ __align__(128) float g_Z2[BNC];
__device__ __align__(128) float g_W [ (size_t)NN*KIO ];
__device__ __align__(128) float g_bias[NN*CC];

// ---------------- helpers ----------------
__device__ __forceinline__ unsigned long long ffma2(unsigned long long a,
                                                    unsigned long long b,
                                                    unsigned long long c) {
    unsigned long long d;
    asm("fma.rn.f32x2 %0, %1, %2, %3;" : "=l"(d) : "l"(a), "l"(b), "l"(c));
    return d;
}
__device__ __forceinline__ unsigned long long pack2(float x, float y) {
    unsigned long long r;
    asm("mov.b64 %0, {%1, %2};" : "=l"(r) : "f"(x), "f"(y));
    return r;
}
__device__ __forceinline__ uint32_t smem_u32(const void* p) {
    uint32_t a;
    asm("{ .reg .u64 t; cvta.to.shared.u64 t, %1; cvt.u32.u64 %0, t; }" : "=r"(a) : "l"(p));
    return a;
}
__device__ __forceinline__ void bsplit(float v, __nv_bfloat16& h, __nv_bfloat16& l) {
    h = __float2bfloat16(v);
    l = __float2bfloat16(v - __bfloat162float(h));
}

// sm_80 baseline async-copy (no 'a'-target features)
#define CP_ASYNC16(dst, src) \
    asm volatile("cp.async.cg.shared.global [%0], [%1], 16;" :: "r"(dst), "l"(src))
#define CP_COMMIT() asm volatile("cp.async.commit_group;" ::: "memory")
#define CP_WAIT1()  asm volatile("cp.async.wait_group 1;" ::: "memory")
#define CP_WAIT0()  asm volatile("cp.async.wait_group 0;" ::: "memory")

#define LDMX4(r0, r1, r2, r3, addr) \
    asm volatile("ldmatrix.sync.aligned.m8n8.x4.shared.b16 {%0,%1,%2,%3}, [%4];" \
        : "=r"(r0), "=r"(r1), "=r"(r2), "=r"(r3) : "r"(addr))

#define MMA16816(d, a, b) \
    asm volatile("mma.sync.aligned.m16n8k16.row.col.f32.bf16.bf16.f32 " \
        "{%0,%1,%2,%3}, {%4,%5,%6,%7}, {%8,%9}, {%0,%1,%2,%3};" \
        : "+f"((d)[0]), "+f"((d)[1]), "+f"((d)[2]), "+f"((d)[3]) \
        : "r"((a)[0]), "r"((a)[1]), "r"((a)[2]), "r"((a)[3]), \
          "r"((b)[0]), "r"((b)[1]))

// ---------------- 1) layernorm over E=16 ----------------
__global__ void ln_kernel(const float* __restrict__ nemb, const float* __restrict__ temb,
                          const float* __restrict__ gamma, const float* __restrict__ beta) {
    int row = blockIdx.x * blockDim.x + threadIdx.x;
    if (row >= NN) return;
    float v[EE];
    float s = 0.f;
    #pragma unroll
    for (int e = 0; e < EE; e++) {
        float x = nemb[row*EE + e] + temb[e];
        v[e] = x; s += x;
    }
    float mu = s * (1.f/EE);
    float s2 = 0.f;
    #pragma unroll
    for (int e = 0; e < EE; e++) { float d = v[e] - mu; s2 += d*d; }
    float inv = rsqrtf(s2 * (1.f/EE) + 1e-12f);
    #pragma unroll
    for (int e = 0; e < EE; e++)
        g_ne[row*EE + e] = (v[e] - mu) * inv * gamma[e] + beta[e];
}

// ---------------- 2) row softmax of ne @ ne^T -> bf16 hi/lo ----------------
__global__ void softmax_kernel() {
    const int n   = blockIdx.x;
    const int tid = threadIdx.x;
    __shared__ float nrow[EE];
    __shared__ float red[8];
    if (tid < EE) nrow[tid] = g_ne[n*EE + tid];
    __syncthreads();

    float l[8];
    float mx = -3.4e38f;
    #pragma unroll
    for (int i = 0; i < 8; i++) {
        int m = tid + i*256;
        const float4* p = (const float4*)&g_ne[m*EE];
        float4 q0 = p[0], q1 = p[1], q2 = p[2], q3 = p[3];
        float d = q0.x*nrow[0] + q0.y*nrow[1] + q0.z*nrow[2] + q0.w*nrow[3]
                + q1.x*nrow[4] + q1.y*nrow[5] + q1.z*nrow[6] + q1.w*nrow[7]
                + q2.x*nrow[8] + q2.y*nrow[9] + q2.z*nrow[10]+ q2.w*nrow[11]
                + q3.x*nrow[12]+ q3.y*nrow[13]+ q3.z*nrow[14]+ q3.w*nrow[15];
        l[i] = d;
        mx = fmaxf(mx, d);
    }
    int lane = tid & 31, wid = tid >> 5;
    #pragma unroll
    for (int o = 16; o; o >>= 1) mx = fmaxf(mx, __shfl_xor_sync(0xffffffffu, mx, o));
    if (lane == 0) red[wid] = mx;
    __syncthreads();
    float bm = red[0];
    #pragma unroll
    for (int w = 1; w < 8; w++) bm = fmaxf(bm, red[w]);

    float s = 0.f;
    #pragma unroll
    for (int i = 0; i < 8; i++) { l[i] = __expf(l[i] - bm); s += l[i]; }
    #pragma unroll
    for (int o = 16; o; o >>= 1) s += __shfl_xor_sync(0xffffffffu, s, o);
    __syncthreads();
    if (lane == 0) red[wid] = s;
    __syncthreads();
    float ts = red[0];
    #pragma unroll
    for (int w = 1; w < 8; w++) ts += red[w];
    float inv = 1.f / ts;
    #pragma unroll
    for (int i = 0; i < 8; i++) {
        float p = l[i] * inv;
        __nv_bfloat16 h, lo;
        bsplit(p, h, lo);
        g_Shi[(size_t)n*NN + tid + i*256] = h;
        g_Slo[(size_t)n*NN + tid + i*256] = lo;
    }
}

// ---------------- 3) x -> Xt hi/lo transpose: Xt[(b*64+c)][n] ----------------
__global__ void xsplit_kernel(const float* __restrict__ x) {
    __shared__ float t[128*65];
    const int b  = blockIdx.y;
    const int n0 = blockIdx.x * 128;
    const int tid = threadIdx.x;
    #pragma unroll
    for (int q = 0; q < 32; q++) {
        int idx = tid + q*256;                  // 0..8191
        int nl = idx >> 6, c = idx & 63;
        t[nl*65 + c] = x[(size_t)b*NN*CC + (size_t)(n0+nl)*CC + c];
    }
    __syncthreads();
    const int c  = tid >> 2;       // 0..63
    const int qt = tid & 3;        // 0..3 -> 32 n each
    __align__(16) __nv_bfloat16 hi[32];
    __align__(16) __nv_bfloat16 lo[32];
    #pragma unroll
    for (int i = 0; i < 32; i++) {
        float v = t[(qt*32 + i)*65 + c];
        bsplit(v, hi[i], lo[i]);
    }
    size_t ro = (size_t)(b*64 + c)*NN + n0 + qt*32;
    uint4* dh = (uint4*)(g_Xthi + ro);
    uint4* dl = (uint4*)(g_Xtlo + ro);
    #pragma unroll
    for (int q = 0; q < 4; q++) { dh[q] = ((uint4*)hi)[q]; dl[q] = ((uint4*)lo)[q]; }
}

// ---------------- 4) per-node weights / bias ----------------
__global__ void wpool_kernel(const float* __restrict__ wpool) {
    __shared__ float wp[EE][64];
    const int tid  = threadIdx.x;
    const int coff = blockIdx.x * 64;
    #pragma unroll
    for (int q = 0; q < 4; q++) {
        int idx = tid + q*256;
        int e = idx >> 6, c = idx & 63;
        wp[e][c] = wpool[e*KIO + coff + c];
    }
    __syncthreads();
    const int r  = tid >> 4;          // 0..15
    const int c4 = (tid & 15) * 4;
    for (int n0 = 0; n0 < NN; n0 += 16) {
        const int n = n0 + r;
        const float* ner = &g_ne[n*EE];
        float a0=0.f, a1=0.f, a2=0.f, a3=0.f;
        #pragma unroll
        for (int e = 0; e < EE; e++) {
            float s = ner[e];
            a0 = fmaf(s, wp[e][c4+0], a0);
            a1 = fmaf(s, wp[e][c4+1], a1);
            a2 = fmaf(s, wp[e][c4+2], a2);
            a3 = fmaf(s, wp[e][c4+3], a3);
        }
        float4 v = make_float4(a0, a1, a2, a3);
        *(float4*)&g_W[(size_t)n*KIO + coff + c4] = v;
    }
}

__global__ void biasp_kernel(const float* __restrict__ bpool) {
    int idx = blockIdx.x * 256 + threadIdx.x;
    int n = idx >> 6, o = idx & 63;
    float a = 0.f;
    #pragma unroll
    for (int e = 0; e < EE; e++) a = fmaf(g_ne[n*EE + e], bpool[e*64 + o], a);
    g_bias[idx] = a;
}

// ---------------- 5) mma.sync GEMM: Z[n, j] = S @ B  (split bf16, fp32 accum) ----------------
// CTA tile 128(M=n) x 128(N=j), K-chunk 32, double-buffered cp.async.
// SMEM row stride 40 bf16 (80 B) -> conflict-free ldmatrix.
#define PADK 40
#define TILEB (128*PADK*2)           // 10240 B per tile
#define OFF_AH 0
#define OFF_AL TILEB
#define OFF_BH (2*TILEB)
#define OFF_BL (3*TILEB)
#define BUFB  (4*TILEB)              // 40960 B
#define GEMM_SMEM (2*BUFB)           // 81920 B
#define KC 32
#define NCH (NN/KC)                  // 64

__global__ __launch_bounds__(256, 1) void gemm_mma(int stage) {
    extern __shared__ __align__(128) char smem[];
    const uint32_t sb = smem_u32(smem);
    const int tid = threadIdx.x;
    const int wid = tid >> 5;
    const int l   = tid & 31;
    const int n0  = blockIdx.x * 128;
    const int jt  = blockIdx.y;

    const __nv_bfloat16* __restrict__ Bhi = stage ? g_Z1thi : g_Xthi;
    const __nv_bfloat16* __restrict__ Blo = stage ? g_Z1tlo : g_Xtlo;
    float* __restrict__ Zf = stage ? g_Z2 : g_Z1;

    const int wm = (wid >> 2) * 64;   // warp M offset (2 rows of warps)
    const int wn = (wid & 3) * 32;    // warp N offset (4 cols of warps)

    // cp.async per-thread coords: 2 segs/thread/tile. s = tid + q*256; row=s>>2, seg=s&3
    const int r0s = tid >> 2, g0 = tid & 3;
    const int r1s = (tid + 256) >> 2, g1 = (tid + 256) & 3;

    // ldmatrix per-thread base offsets
    const uint32_t a_ro = (uint32_t)(wm + (l & 15)) * (PADK*2) + (uint32_t)(l >> 4) * 16;
    const uint32_t b_ro = (uint32_t)(wn + (l & 7) + ((l >> 4) << 3)) * (PADK*2)
                        + (uint32_t)((l >> 3) & 1) * 16;

    float acc[4][4][4];
    #pragma unroll
    for (int mi = 0; mi < 4; mi++)
        #pragma unroll
        for (int ni = 0; ni < 4; ni++)
            #pragma unroll
            for (int q = 0; q < 4; q++) acc[mi][ni][q] = 0.f;

    // ---- async load issue for chunk kt into buffer buf ----
    auto issue = [&](int kt, int buf) {
        const int kb = kt * KC;
        const uint32_t bo = sb + buf*BUFB;
        const uint32_t d0 = bo + (uint32_t)r0s*(PADK*2) + (uint32_t)g0*16;
        const uint32_t d1 = bo + (uint32_t)r1s*(PADK*2) + (uint32_t)g1*16;
        const __nv_bfloat16* a0h = g_Shi + (size_t)(n0 + r0s)*NN + kb + g0*8;
        const __nv_bfloat16* a0l = g_Slo + (size_t)(n0 + r0s)*NN + kb + g0*8;
        const __nv_bfloat16* a1h = g_Shi + (size_t)(n0 + r1s)*NN + kb + g1*8;
        const __nv_bfloat16* a1l = g_Slo + (size_t)(n0 + r1s)*NN + kb + g1*8;
        const __nv_bfloat16* b0h = Bhi + (size_t)(jt*128 + r0s)*NN + kb + g0*8;
        const __nv_bfloat16* b0l = Blo + (size_t)(jt*128 + r0s)*NN + kb + g0*8;
        const __nv_bfloat16* b1h = Bhi + (size_t)(jt*128 + r1s)*NN + kb + g1*8;
        const __nv_bfloat16* b1l = Blo + (size_t)(jt*128 + r1s)*NN + kb + g1*8;
        CP_ASYNC16(d0 + OFF_AH, a0h);  CP_ASYNC16(d1 + OFF_AH, a1h);
        CP_ASYNC16(d0 + OFF_AL, a0l);  CP_ASYNC16(d1 + OFF_AL, a1l);
        CP_ASYNC16(d0 + OFF_BH, b0h);  CP_ASYNC16(d1 + OFF_BH, b1h);
        CP_ASYNC16(d0 + OFF_BL, b0l);  CP_ASYNC16(d1 + OFF_BL, b1l);
        CP_COMMIT();
    };

    issue(0, 0);

    for (int kt = 0; kt < NCH; kt++) {
        const int buf = kt & 1;
        if (kt + 1 < NCH) { issue(kt + 1, buf ^ 1); CP_WAIT1(); }
        else              { CP_WAIT0(); }
        __syncthreads();

        const uint32_t abase = sb + buf*BUFB + a_ro;
        const uint32_t bbase = sb + buf*BUFB + b_ro;

        #pragma unroll
        for (int ks = 0; ks < 2; ks++) {
            uint32_t ah[4][4], al[4][4];
            #pragma unroll
            for (int mi = 0; mi < 4; mi++) {
                LDMX4(ah[mi][0], ah[mi][1], ah[mi][2], ah[mi][3],
                      abase + OFF_AH + mi*(16*PADK*2) + ks*32);
                LDMX4(al[mi][0], al[mi][1], al[mi][2], al[mi][3],
                      abase + OFF_AL + mi*(16*PADK*2) + ks*32);
            }
            uint32_t bh[4][2], bl[4][2];
            #pragma unroll
            for (int p = 0; p < 2; p++) {
                LDMX4(bh[2*p][0], bh[2*p][1], bh[2*p+1][0], bh[2*p+1][1],
                      bbase + OFF_BH + p*(16*PADK*2) + ks*32);
                LDMX4(bl[2*p][0], bl[2*p][1], bl[2*p+1][0], bl[2*p+1][1],
                      bbase + OFF_BL + p*(16*PADK*2) + ks*32);
            }
            #pragma unroll
            for (int mi = 0; mi < 4; mi++)
                #pragma unroll
                for (int ni = 0; ni < 4; ni++) {
                    MMA16816(acc[mi][ni], ah[mi], bh[ni]);
                    MMA16816(acc[mi][ni], ah[mi], bl[ni]);
                    MMA16816(acc[mi][ni], al[mi], bh[ni]);
                }
        }
        __syncthreads();
    }

    // ---- epilogue: fp32 Z store ----
    const int rsub = l >> 2;            // 0..7
    const int csub = 2 * (l & 3);       // 0,2,4,6
    #pragma unroll
    for (int mi = 0; mi < 4; mi++) {
        const int node = n0 + wm + mi*16 + rsub;
        #pragma unroll
        for (int ni = 0; ni < 4; ni++) {
            const int jl = wn + ni*8 + csub;
            const int j  = jt*128 + jl;
            const int b  = j >> 6, c = j & 63;
            float2 v01; v01.x = acc[mi][ni][0]; v01.y = acc[mi][ni][1];
            float2 v23; v23.x = acc[mi][ni][2]; v23.y = acc[mi][ni][3];
            *(float2*)&Zf[(size_t)b*(NN*CC) + (size_t)node*CC + c]      = v01;
            *(float2*)&Zf[(size_t)b*(NN*CC) + (size_t)(node+8)*CC + c]  = v23;
        }
    }

    // ---- stage 0: bounce Z1 through smem -> bf16 hi/lo transposed [j][n] ----
    if (stage == 0) {
        __syncthreads();
        __nv_bfloat16* Thi = (__nv_bfloat16*)smem;        // [128][136]
        __nv_bfloat16* Tlo = Thi + 128*136;
        #pragma unroll
        for (int mi = 0; mi < 4; mi++) {
            const int nl = wm + mi*16 + rsub;
            #pragma unroll
            for (int ni = 0; ni < 4; ni++) {
                const int jl = wn + ni*8 + csub;
                __nv_bfloat16 h, lo;
                bsplit(acc[mi][ni][0], h, lo);
                Thi[jl*136 + nl] = h;        Tlo[jl*136 + nl] = lo;
                bsplit(acc[mi][ni][1], h, lo);
                Thi[(jl+1)*136 + nl] = h;    Tlo[(jl+1)*136 + nl] = lo;
                bsplit(acc[mi][ni][2], h, lo);
                Thi[jl*136 + nl + 8] = h;    Tlo[jl*136 + nl + 8] = lo;
                bsplit(acc[mi][ni][3], h, lo);
                Thi[(jl+1)*136 + nl + 8] = h; Tlo[(jl+1)*136 + nl + 8] = lo;
            }
        }
        __syncthreads();
        const int jl = tid >> 1, half = tid & 1;
        const size_t ro = (size_t)(jt*128 + jl)*NN + n0 + half*64;
        const uint4* sh = (const uint4*)&Thi[jl*136 + half*64];
        const uint4* sl = (const uint4*)&Tlo[jl*136 + half*64];
        uint4* dh = (uint4*)(g_Z1thi + ro);
        uint4* dl = (uint4*)(g_Z1tlo + ro);
        #pragma unroll
        for (int q = 0; q < 8; q++) { dh[q] = sh[q]; dl[q] = sl[q]; }
    }
}

// ---------------- 6) final: Y[b,n,o] = XG[b,:] @ W_n + bias_n ----------------
#define XGS 196
#define FIN_SMEM ((KIO + BB*XGS) * 4)

__global__ __launch_bounds__(256, 2) void final_kernel(const float* __restrict__ X,
                                                       float* __restrict__ out) {
    extern __shared__ __align__(16) float sm[];
    float* Ws = sm;            // [192][64]
    float* XG = sm + KIO;      // [64][XGS]
    const int n   = blockIdx.x;
    const int tid = threadIdx.x;

    const float4* wsrc = (const float4*)(g_W + (size_t)n*KIO);
    float4* wdst = (float4*)Ws;
    #pragma unroll
    for (int q = 0; q < 12; q++) wdst[tid + q*256] = wsrc[tid + q*256];

    #pragma unroll
    for (int q = 0; q < 4; q++) {
        int f = tid + q*256;
        int b = f >> 4, c4 = (f & 15) * 4;
        size_t off = (size_t)b*NN*CC + (size_t)n*CC + c4;
        float4 xv = *(const float4*)&X[off];
        float4 z1 = *(const float4*)&g_Z1[off];
        float4 z2 = *(const float4*)&g_Z2[off];
        float4 g2;
        g2.x = 2.f*z2.x - xv.x; g2.y = 2.f*z2.y - xv.y;
        g2.z = 2.f*z2.z - xv.z; g2.w = 2.f*z2.w - xv.w;
        *(float4*)&XG[b*XGS + c4]       = xv;
        *(float4*)&XG[b*XGS + 64 + c4]  = z1;
        *(float4*)&XG[b*XGS + 128 + c4] = g2;
    }
    __syncthreads();

    const int tx = tid & 7, o0 = tx * 8;
    const int b0 = (tid >> 3) * 2;

    unsigned long long acc[2][4];
    {
        const ulonglong2* bp = (const ulonglong2*)(g_bias + (size_t)n*CC + o0);
        ulonglong2 p0 = bp[0], p1 = bp[1];
        acc[0][0]=p0.x; acc[0][1]=p0.y; acc[0][2]=p1.x; acc[0][3]=p1.y;
        acc[1][0]=p0.x; acc[1][1]=p0.y; acc[1][2]=p1.x; acc[1][3]=p1.y;
    }
    const float* xr0 = &XG[b0*XGS];
    const float* xr1 = &XG[(b0+1)*XGS];
    #pragma unroll 4
    for (int i = 0; i < 192; i++) {
        ulonglong2 w0 = *(const ulonglong2*)&Ws[i*64 + o0];
        ulonglong2 w1 = *(const ulonglong2*)&Ws[i*64 + o0 + 4];
        unsigned long long x0 = pack2(xr0[i], xr0[i]);
        unsigned long long x1 = pack2(xr1[i], xr1[i]);
        acc[0][0] = ffma2(x0, w0.x, acc[0][0]);
        acc[0][1] = ffma2(x0, w0.y, acc[0][1]);
        acc[0][2] = ffma2(x0, w1.x, acc[0][2]);
        acc[0][3] = ffma2(x0, w1.y, acc[0][3]);
        acc[1][0] = ffma2(x1, w0.x, acc[1][0]);
        acc[1][1] = ffma2(x1, w0.y, acc[1][1]);
        acc[1][2] = ffma2(x1, w1.x, acc[1][2]);
        acc[1][3] = ffma2(x1, w1.y, acc[1][3]);
    }
    #pragma unroll
    for (int bb = 0; bb < 2; bb++)
        #pragma unroll
        for (int jp = 0; jp < 4; jp++)
            *(unsigned long long*)&out[(size_t)(b0+bb)*NN*CC + (size_t)n*CC + o0 + jp*2] = acc[bb][jp];
}

// ---------------- launcher ----------------
extern "C" void kernel_launch(void* const* d_in, const int* in_sizes, int n_in,
                              void* d_out, int out_size) {
    const float* x     = (const float*)d_in[0];
    const float* nemb  = (const float*)d_in[1];
    const float* temb  = (const float*)d_in[2];
    const float* wpool = (const float*)d_in[3];
    const float* bpool = (const float*)d_in[4];
    const float* gamma = (const float*)d_in[5];
    const float* beta  = (const float*)d_in[6];
    float* out = (float*)d_out;

    cudaFuncSetAttribute(final_kernel, cudaFuncAttributeMaxDynamicSharedMemorySize, FIN_SMEM);
    cudaFuncSetAttribute(gemm_mma, cudaFuncAttributeMaxDynamicSharedMemorySize, GEMM_SMEM);

    ln_kernel<<<16, 128>>>(nemb, temb, gamma, beta);
    softmax_kernel<<<NN, 256>>>();
    xsplit_kernel<<<dim3(16, 64), 256>>>(x);
    wpool_kernel<<<192, 256>>>(wpool);
    biasp_kernel<<<512, 256>>>(bpool);
    gemm_mma<<<dim3(16, 32), 256, GEMM_SMEM>>>(0);
    gemm_mma<<<dim3(16, 32), 256, GEMM_SMEM>>>(1);
    final_kernel<<<NN, 256, FIN_SMEM>>>(x, out);
}

// round 15
// speedup vs baseline: 1.9728x; 1.0594x over previous
#include <cuda_runtime.h>
#include <cuda_bf16.h>
#include <cstdint>

#define NN 2048
#define BB 64
#define CC 64
#define EE 16
#define KIO 12288   // 3*64*64
#define BNC (BB*NN*CC)
#define JJ  (BB*CC)   // 4096

// ---------------- scratch (device globals; no allocations allowed) ----------------
__device__ __align__(128) float g_ne[NN*EE];
__device__ __align__(128) __nv_bfloat16 g_Shi[NN*NN];
__device__ __align__(128) __nv_bfloat16 g_Slo[NN*NN];
__device__ __align__(128) __nv_bfloat16 g_Xthi[(size_t)JJ*NN];
__device__ __align__(128) __nv_bfloat16 g_Xtlo[(size_t)JJ*NN];
__device__ __align__(128) __nv_bfloat16 g_Z1thi[(size_t)JJ*NN];
__device__ __align__(128) __nv_bfloat16 g_Z1tlo[(size_t)JJ*NN];
__device__ __align__(128) float g_Z1[BNC];
__device__ __align__(128) float g_Z2[BNC];
__device__ __align__(128) float g_W [ (size_t)NN*KIO ];
__device__ __align__(128) float g_bias[NN*CC];

// ---------------- helpers ----------------
__device__ __forceinline__ unsigned long long ffma2(unsigned long long a,
                                                    unsigned long long b,
                                                    unsigned long long c) {
    unsigned long long d;
    asm("fma.rn.f32x2 %0, %1, %2, %3;" : "=l"(d) : "l"(a), "l"(b), "l"(c));
    return d;
}
__device__ __forceinline__ unsigned long long pack2(float x, float y) {
    unsigned long long r;
    asm("mov.b64 %0, {%1, %2};" : "=l"(r) : "f"(x), "f"(y));
    return r;
}
__device__ __forceinline__ uint32_t smem_u32(const void* p) {
    uint32_t a;
    asm("{ .reg .u64 t; cvta.to.shared.u64 t, %1; cvt.u32.u64 %0, t; }" : "=r"(a) : "l"(p));
    return a;
}
__device__ __forceinline__ void bsplit(float v, __nv_bfloat16& h, __nv_bfloat16& l) {
    h = __float2bfloat16(v);
    l = __float2bfloat16(v - __bfloat162float(h));
}

// sm_80 baseline async-copy (no 'a'-target features)
#define CP_ASYNC16(dst, src) \
    asm volatile("cp.async.cg.shared.global [%0], [%1], 16;" :: "r"(dst), "l"(src))
#define CP_COMMIT() asm volatile("cp.async.commit_group;" ::: "memory")
#define CP_WAIT1()  asm volatile("cp.async.wait_group 1;" ::: "memory")
#define CP_WAIT0()  asm volatile("cp.async.wait_group 0;" ::: "memory")

#define LDMX4(r0, r1, r2, r3, addr) \
    asm volatile("ldmatrix.sync.aligned.m8n8.x4.shared.b16 {%0,%1,%2,%3}, [%4];" \
        : "=r"(r0), "=r"(r1), "=r"(r2), "=r"(r3) : "r"(addr))

#define MMA16816(d, a, b) \
    asm volatile("mma.sync.aligned.m16n8k16.row.col.f32.bf16.bf16.f32 " \
        "{%0,%1,%2,%3}, {%4,%5,%6,%7}, {%8,%9}, {%0,%1,%2,%3};" \
        : "+f"((d)[0]), "+f"((d)[1]), "+f"((d)[2]), "+f"((d)[3]) \
        : "r"((a)[0]), "r"((a)[1]), "r"((a)[2]), "r"((a)[3]), \
          "r"((b)[0]), "r"((b)[1]))

// ---------------- 1) layernorm over E=16 ----------------
__global__ void ln_kernel(const float* __restrict__ nemb, const float* __restrict__ temb,
                          const float* __restrict__ gamma, const float* __restrict__ beta) {
    int row = blockIdx.x * blockDim.x + threadIdx.x;
    if (row >= NN) return;
    float v[EE];
    float s = 0.f;
    #pragma unroll
    for (int e = 0; e < EE; e++) {
        float x = nemb[row*EE + e] + temb[e];
        v[e] = x; s += x;
    }
    float mu = s * (1.f/EE);
    float s2 = 0.f;
    #pragma unroll
    for (int e = 0; e < EE; e++) { float d = v[e] - mu; s2 += d*d; }
    float inv = rsqrtf(s2 * (1.f/EE) + 1e-12f);
    #pragma unroll
    for (int e = 0; e < EE; e++)
        g_ne[row*EE + e] = (v[e] - mu) * inv * gamma[e] + beta[e];
}

// ---------------- 2) row softmax of ne @ ne^T -> bf16 hi/lo ----------------
__global__ void softmax_kernel() {
    const int n   = blockIdx.x;
    const int tid = threadIdx.x;
    __shared__ float nrow[EE];
    __shared__ float red[8];
    if (tid < EE) nrow[tid] = g_ne[n*EE + tid];
    __syncthreads();

    float l[8];
    float mx = -3.4e38f;
    #pragma unroll
    for (int i = 0; i < 8; i++) {
        int m = tid + i*256;
        const float4* p = (const float4*)&g_ne[m*EE];
        float4 q0 = p[0], q1 = p[1], q2 = p[2], q3 = p[3];
        float d = q0.x*nrow[0] + q0.y*nrow[1] + q0.z*nrow[2] + q0.w*nrow[3]
                + q1.x*nrow[4] + q1.y*nrow[5] + q1.z*nrow[6] + q1.w*nrow[7]
                + q2.x*nrow[8] + q2.y*nrow[9] + q2.z*nrow[10]+ q2.w*nrow[11]
                + q3.x*nrow[12]+ q3.y*nrow[13]+ q3.z*nrow[14]+ q3.w*nrow[15];
        l[i] = d;
        mx = fmaxf(mx, d);
    }
    int lane = tid & 31, wid = tid >> 5;
    #pragma unroll
    for (int o = 16; o; o >>= 1) mx = fmaxf(mx, __shfl_xor_sync(0xffffffffu, mx, o));
    if (lane == 0) red[wid] = mx;
    __syncthreads();
    float bm = red[0];
    #pragma unroll
    for (int w = 1; w < 8; w++) bm = fmaxf(bm, red[w]);

    float s = 0.f;
    #pragma unroll
    for (int i = 0; i < 8; i++) { l[i] = __expf(l[i] - bm); s += l[i]; }
    #pragma unroll
    for (int o = 16; o; o >>= 1) s += __shfl_xor_sync(0xffffffffu, s, o);
    __syncthreads();
    if (lane == 0) red[wid] = s;
    __syncthreads();
    float ts = red[0];
    #pragma unroll
    for (int w = 1; w < 8; w++) ts += red[w];
    float inv = 1.f / ts;
    #pragma unroll
    for (int i = 0; i < 8; i++) {
        float p = l[i] * inv;
        __nv_bfloat16 h, lo;
        bsplit(p, h, lo);
        g_Shi[(size_t)n*NN + tid + i*256] = h;
        g_Slo[(size_t)n*NN + tid + i*256] = lo;
    }
}

// ---------------- 3) x -> Xt hi/lo transpose: Xt[(b*64+c)][n] ----------------
__global__ void xsplit_kernel(const float* __restrict__ x) {
    __shared__ float t[128*65];
    const int b  = blockIdx.y;
    const int n0 = blockIdx.x * 128;
    const int tid = threadIdx.x;
    #pragma unroll
    for (int q = 0; q < 32; q++) {
        int idx = tid + q*256;                  // 0..8191
        int nl = idx >> 6, c = idx & 63;
        t[nl*65 + c] = x[(size_t)b*NN*CC + (size_t)(n0+nl)*CC + c];
    }
    __syncthreads();
    const int c  = tid >> 2;       // 0..63
    const int qt = tid & 3;        // 0..3 -> 32 n each
    __align__(16) __nv_bfloat16 hi[32];
    __align__(16) __nv_bfloat16 lo[32];
    #pragma unroll
    for (int i = 0; i < 32; i++) {
        float v = t[(qt*32 + i)*65 + c];
        bsplit(v, hi[i], lo[i]);
    }
    size_t ro = (size_t)(b*64 + c)*NN + n0 + qt*32;
    uint4* dh = (uint4*)(g_Xthi + ro);
    uint4* dl = (uint4*)(g_Xtlo + ro);
    #pragma unroll
    for (int q = 0; q < 4; q++) { dh[q] = ((uint4*)hi)[q]; dl[q] = ((uint4*)lo)[q]; }
}

// ---------------- 4) per-node weights / bias ----------------
// grid (192, 8): block covers 64 kio-cols x 256 nodes -> 1536 blocks (vs 192)
__global__ void wpool_kernel(const float* __restrict__ wpool) {
    __shared__ float wp[EE][64];
    const int tid  = threadIdx.x;
    const int coff = blockIdx.x * 64;
    const int nbase = blockIdx.y * 256;
    #pragma unroll
    for (int q = 0; q < 4; q++) {
        int idx = tid + q*256;
        int e = idx >> 6, c = idx & 63;
        wp[e][c] = wpool[e*KIO + coff + c];
    }
    __syncthreads();
    const int r  = tid >> 4;          // 0..15
    const int c4 = (tid & 15) * 4;
    for (int n0 = 0; n0 < 256; n0 += 16) {
        const int n = nbase + n0 + r;
        const float* ner = &g_ne[n*EE];
        float a0=0.f, a1=0.f, a2=0.f, a3=0.f;
        #pragma unroll
        for (int e = 0; e < EE; e++) {
            float s = ner[e];
            a0 = fmaf(s, wp[e][c4+0], a0);
            a1 = fmaf(s, wp[e][c4+1], a1);
            a2 = fmaf(s, wp[e][c4+2], a2);
            a3 = fmaf(s, wp[e][c4+3], a3);
        }
        float4 v = make_float4(a0, a1, a2, a3);
        *(float4*)&g_W[(size_t)n*KIO + coff + c4] = v;
    }
}

__global__ void biasp_kernel(const float* __restrict__ bpool) {
    int idx = blockIdx.x * 256 + threadIdx.x;
    int n = idx >> 6, o = idx & 63;
    float a = 0.f;
    #pragma unroll
    for (int e = 0; e < EE; e++) a = fmaf(g_ne[n*EE + e], bpool[e*64 + o], a);
    g_bias[idx] = a;
}

// ---------------- 5) mma.sync GEMM: Z[n, j] = S @ B  (split bf16, fp32 accum) ----------------
// CTA tile 128(M=n) x 128(N=j), K-chunk 32, double-buffered cp.async, 2 CTAs/SM.
// SMEM row stride 40 bf16 (80 B) -> conflict-free ldmatrix.
#define PADK 40
#define TILEB (128*PADK*2)           // 10240 B per tile
#define OFF_AH 0
#define OFF_AL TILEB
#define OFF_BH (2*TILEB)
#define OFF_BL (3*TILEB)
#define BUFB  (4*TILEB)              // 40960 B
#define GEMM_SMEM (2*BUFB)           // 81920 B
#define KC 32
#define NCH (NN/KC)                  // 64

__global__ __launch_bounds__(256, 2) void gemm_mma(int stage) {
    extern __shared__ __align__(128) char smem[];
    const uint32_t sb = smem_u32(smem);
    const int tid = threadIdx.x;
    const int wid = tid >> 5;
    const int l   = tid & 31;
    const int n0  = blockIdx.x * 128;
    const int jt  = blockIdx.y;

    const __nv_bfloat16* __restrict__ Bhi = stage ? g_Z1thi : g_Xthi;
    const __nv_bfloat16* __restrict__ Blo = stage ? g_Z1tlo : g_Xtlo;
    float* __restrict__ Zf = stage ? g_Z2 : g_Z1;

    const int wm = (wid >> 2) * 64;   // warp M offset (2 rows of warps)
    const int wn = (wid & 3) * 32;    // warp N offset (4 cols of warps)

    // cp.async per-thread coords: 2 segs/thread/tile. s = tid + q*256; row=s>>2, seg=s&3
    const int r0s = tid >> 2, g0 = tid & 3;
    const int r1s = (tid + 256) >> 2, g1 = (tid + 256) & 3;

    // ldmatrix per-thread base offsets
    const uint32_t a_ro = (uint32_t)(wm + (l & 15)) * (PADK*2) + (uint32_t)(l >> 4) * 16;
    const uint32_t b_ro = (uint32_t)(wn + (l & 7) + ((l >> 4) << 3)) * (PADK*2)
                        + (uint32_t)((l >> 3) & 1) * 16;

    float acc[4][4][4];
    #pragma unroll
    for (int mi = 0; mi < 4; mi++)
        #pragma unroll
        for (int ni = 0; ni < 4; ni++)
            #pragma unroll
            for (int q = 0; q < 4; q++) acc[mi][ni][q] = 0.f;

    // ---- async load issue for chunk kt into buffer buf ----
    auto issue = [&](int kt, int buf) {
        const int kb = kt * KC;
        const uint32_t bo = sb + buf*BUFB;
        const uint32_t d0 = bo + (uint32_t)r0s*(PADK*2) + (uint32_t)g0*16;
        const uint32_t d1 = bo + (uint32_t)r1s*(PADK*2) + (uint32_t)g1*16;
        const __nv_bfloat16* a0h = g_Shi + (size_t)(n0 + r0s)*NN + kb + g0*8;
        const __nv_bfloat16* a0l = g_Slo + (size_t)(n0 + r0s)*NN + kb + g0*8;
        const __nv_bfloat16* a1h = g_Shi + (size_t)(n0 + r1s)*NN + kb + g1*8;
        const __nv_bfloat16* a1l = g_Slo + (size_t)(n0 + r1s)*NN + kb + g1*8;
        const __nv_bfloat16* b0h = Bhi + (size_t)(jt*128 + r0s)*NN + kb + g0*8;
        const __nv_bfloat16* b0l = Blo + (size_t)(jt*128 + r0s)*NN + kb + g0*8;
        const __nv_bfloat16* b1h = Bhi + (size_t)(jt*128 + r1s)*NN + kb + g1*8;
        const __nv_bfloat16* b1l = Blo + (size_t)(jt*128 + r1s)*NN + kb + g1*8;
        CP_ASYNC16(d0 + OFF_AH, a0h);  CP_ASYNC16(d1 + OFF_AH, a1h);
        CP_ASYNC16(d0 + OFF_AL, a0l);  CP_ASYNC16(d1 + OFF_AL, a1l);
        CP_ASYNC16(d0 + OFF_BH, b0h);  CP_ASYNC16(d1 + OFF_BH, b1h);
        CP_ASYNC16(d0 + OFF_BL, b0l);  CP_ASYNC16(d1 + OFF_BL, b1l);
        CP_COMMIT();
    };

    issue(0, 0);

    for (int kt = 0; kt < NCH; kt++) {
        const int buf = kt & 1;
        if (kt + 1 < NCH) { issue(kt + 1, buf ^ 1); CP_WAIT1(); }
        else              { CP_WAIT0(); }
        __syncthreads();

        const uint32_t abase = sb + buf*BUFB + a_ro;
        const uint32_t bbase = sb + buf*BUFB + b_ro;

        #pragma unroll
        for (int ks = 0; ks < 2; ks++) {
            uint32_t bh[4][2], bl[4][2];
            #pragma unroll
            for (int p = 0; p < 2; p++) {
                LDMX4(bh[2*p][0], bh[2*p][1], bh[2*p+1][0], bh[2*p+1][1],
                      bbase + OFF_BH + p*(16*PADK*2) + ks*32);
                LDMX4(bl[2*p][0], bl[2*p][1], bl[2*p+1][0], bl[2*p+1][1],
                      bbase + OFF_BL + p*(16*PADK*2) + ks*32);
            }
            // per-mi A-fragment load keeps live regs under the 128-reg 2-CTA cap
            #pragma unroll
            for (int mi = 0; mi < 4; mi++) {
                uint32_t ah[4], al[4];
                LDMX4(ah[0], ah[1], ah[2], ah[3],
                      abase + OFF_AH + mi*(16*PADK*2) + ks*32);
                LDMX4(al[0], al[1], al[2], al[3],
                      abase + OFF_AL + mi*(16*PADK*2) + ks*32);
                #pragma unroll
                for (int ni = 0; ni < 4; ni++) {
                    MMA16816(acc[mi][ni], ah, bh[ni]);
                    MMA16816(acc[mi][ni], ah, bl[ni]);
                    MMA16816(acc[mi][ni], al, bh[ni]);
                }
            }
        }
        __syncthreads();
    }

    // ---- epilogue: fp32 Z store ----
    const int rsub = l >> 2;            // 0..7
    const int csub = 2 * (l & 3);       // 0,2,4,6
    #pragma unroll
    for (int mi = 0; mi < 4; mi++) {
        const int node = n0 + wm + mi*16 + rsub;
        #pragma unroll
        for (int ni = 0; ni < 4; ni++) {
            const int jl = wn + ni*8 + csub;
            const int j  = jt*128 + jl;
            const int b  = j >> 6, c = j & 63;
            float2 v01; v01.x = acc[mi][ni][0]; v01.y = acc[mi][ni][1];
            float2 v23; v23.x = acc[mi][ni][2]; v23.y = acc[mi][ni][3];
            *(float2*)&Zf[(size_t)b*(NN*CC) + (size_t)node*CC + c]      = v01;
            *(float2*)&Zf[(size_t)b*(NN*CC) + (size_t)(node+8)*CC + c]  = v23;
        }
    }

    // ---- stage 0: bounce Z1 through smem -> bf16 hi/lo transposed [j][n] ----
    if (stage == 0) {
        __syncthreads();
        __nv_bfloat16* Thi = (__nv_bfloat16*)smem;        // [128][136]
        __nv_bfloat16* Tlo = Thi + 128*136;
        #pragma unroll
        for (int mi = 0; mi < 4; mi++) {
            const int nl = wm + mi*16 + rsub;
            #pragma unroll
            for (int ni = 0; ni < 4; ni++) {
                const int jl = wn + ni*8 + csub;
                __nv_bfloat16 h, lo;
                bsplit(acc[mi][ni][0], h, lo);
                Thi[jl*136 + nl] = h;        Tlo[jl*136 + nl] = lo;
                bsplit(acc[mi][ni][1], h, lo);
                Thi[(jl+1)*136 + nl] = h;    Tlo[(jl+1)*136 + nl] = lo;
                bsplit(acc[mi][ni][2], h, lo);
                Thi[jl*136 + nl + 8] = h;    Tlo[jl*136 + nl + 8] = lo;
                bsplit(acc[mi][ni][3], h, lo);
                Thi[(jl+1)*136 + nl + 8] = h; Tlo[(jl+1)*136 + nl + 8] = lo;
            }
        }
        __syncthreads();
        const int jl = tid >> 1, half = tid & 1;
        const size_t ro = (size_t)(jt*128 + jl)*NN + n0 + half*64;
        const uint4* sh = (const uint4*)&Thi[jl*136 + half*64];
        const uint4* sl = (const uint4*)&Tlo[jl*136 + half*64];
        uint4* dh = (uint4*)(g_Z1thi + ro);
        uint4* dl = (uint4*)(g_Z1tlo + ro);
        #pragma unroll
        for (int q = 0; q < 8; q++) { dh[q] = sh[q]; dl[q] = sl[q]; }
    }
}

// ---------------- 6) final: Y[b,n,o] = XG[b,:] @ W_n + bias_n ----------------
#define XGS 196
#define FIN_SMEM ((KIO + BB*XGS) * 4)

__global__ __launch_bounds__(256, 2) void final_kernel(const float* __restrict__ X,
                                                       float* __restrict__ out) {
    extern __shared__ __align__(16) float sm[];
    float* Ws = sm;            // [192][64]
    float* XG = sm + KIO;      // [64][XGS]
    const int n   = blockIdx.x;
    const int tid = threadIdx.x;

    const float4* wsrc = (const float4*)(g_W + (size_t)n*KIO);
    float4* wdst = (float4*)Ws;
    #pragma unroll
    for (int q = 0; q < 12; q++) wdst[tid + q*256] = wsrc[tid + q*256];

    #pragma unroll
    for (int q = 0; q < 4; q++) {
        int f = tid + q*256;
        int b = f >> 4, c4 = (f & 15) * 4;
        size_t off = (size_t)b*NN*CC + (size_t)n*CC + c4;
        float4 xv = *(const float4*)&X[off];
        float4 z1 = *(const float4*)&g_Z1[off];
        float4 z2 = *(const float4*)&g_Z2[off];
        float4 g2;
        g2.x = 2.f*z2.x - xv.x; g2.y = 2.f*z2.y - xv.y;
        g2.z = 2.f*z2.z - xv.z; g2.w = 2.f*z2.w - xv.w;
        *(float4*)&XG[b*XGS + c4]       = xv;
        *(float4*)&XG[b*XGS + 64 + c4]  = z1;
        *(float4*)&XG[b*XGS + 128 + c4] = g2;
    }
    __syncthreads();

    const int tx = tid & 7, o0 = tx * 8;
    const int b0 = (tid >> 3) * 2;

    unsigned long long acc[2][4];
    {
        const ulonglong2* bp = (const ulonglong2*)(g_bias + (size_t)n*CC + o0);
        ulonglong2 p0 = bp[0], p1 = bp[1];
        acc[0][0]=p0.x; acc[0][1]=p0.y; acc[0][2]=p1.x; acc[0][3]=p1.y;
        acc[1][0]=p0.x; acc[1][1]=p0.y; acc[1][2]=p1.x; acc[1][3]=p1.y;
    }
    const float* xr0 = &XG[b0*XGS];
    const float* xr1 = &XG[(b0+1)*XGS];
    #pragma unroll 4
    for (int i = 0; i < 192; i++) {
        ulonglong2 w0 = *(const ulonglong2*)&Ws[i*64 + o0];
        ulonglong2 w1 = *(const ulonglong2*)&Ws[i*64 + o0 + 4];
        unsigned long long x0 = pack2(xr0[i], xr0[i]);
        unsigned long long x1 = pack2(xr1[i], xr1[i]);
        acc[0][0] = ffma2(x0, w0.x, acc[0][0]);
        acc[0][1] = ffma2(x0, w0.y, acc[0][1]);
        acc[0][2] = ffma2(x0, w1.x, acc[0][2]);
        acc[0][3] = ffma2(x0, w1.y, acc[0][3]);
        acc[1][0] = ffma2(x1, w0.x, acc[1][0]);
        acc[1][1] = ffma2(x1, w0.y, acc[1][1]);
        acc[1][2] = ffma2(x1, w1.x, acc[1][2]);
        acc[1][3] = ffma2(x1, w1.y, acc[1][3]);
    }
    #pragma unroll
    for (int bb = 0; bb < 2; bb++)
        #pragma unroll
        for (int jp = 0; jp < 4; jp++)
            *(unsigned long long*)&out[(size_t)(b0+bb)*NN*CC + (size_t)n*CC + o0 + jp*2] = acc[bb][jp];
}

// ---------------- launcher ----------------
extern "C" void kernel_launch(void* const* d_in, const int* in_sizes, int n_in,
                              void* d_out, int out_size) {
    const float* x     = (const float*)d_in[0];
    const float* nemb  = (const float*)d_in[1];
    const float* temb  = (const float*)d_in[2];
    const float* wpool = (const float*)d_in[3];
    const float* bpool = (const float*)d_in[4];
    const float* gamma = (const float*)d_in[5];
    const float* beta  = (const float*)d_in[6];
    float* out = (float*)d_out;

    cudaFuncSetAttribute(final_kernel, cudaFuncAttributeMaxDynamicSharedMemorySize, FIN_SMEM);
    cudaFuncSetAttribute(gemm_mma, cudaFuncAttributeMaxDynamicSharedMemorySize, GEMM_SMEM);

    ln_kernel<<<16, 128>>>(nemb, temb, gamma, beta);
    softmax_kernel<<<NN, 256>>>();
    xsplit_kernel<<<dim3(16, 64), 256>>>(x);
    wpool_kernel<<<dim3(192, 8), 256>>>(wpool);
    biasp_kernel<<<512, 256>>>(bpool);
    gemm_mma<<<dim3(16, 32), 256, GEMM_SMEM>>>(0);
    gemm_mma<<<dim3(16, 32), 256, GEMM_SMEM>>>(1);
    final_kernel<<<NN, 256, FIN_SMEM>>>(x, out);
}